// round 2
// baseline (speedup 1.0000x reference)
#include <cuda_runtime.h>

#define BB 128
#define NN 512
#define CF 64
#define ALPHA_ 0.2f
#define WTS_STRIDE 33

// scratch (allocation-free rule: __device__ globals)
__device__ __align__(16) float g_h1[BB * NN * CF];
__device__ __align__(16) float g_diff[BB * NN * CF];
__device__ float g_s1[BB * NN];
__device__ float g_s2[BB * NN];

// ---------------------------------------------------------------------------
// Kernel 1: h0 = x@W0, h1 = x@W1 ; store h1, diff=h0-h1, s1=(h0+h1)@a1, s2=...@a2
// 256 threads, 64 rows per block, grid = 65536/64 = 1024
// ---------------------------------------------------------------------------
__global__ __launch_bounds__(256) void gat_gemm_kernel(
    const float* __restrict__ x, const float* __restrict__ W,
    const float* __restrict__ a)
{
    __shared__ float W0s[CF * CF];
    __shared__ float W1s[CF * CF];
    __shared__ float xs[16 * CF];
    __shared__ float redbuf[16][2][2];

    int t = threadIdx.x;
    for (int idx = t; idx < CF * CF; idx += 256) {
        W0s[idx] = W[idx];
        W1s[idx] = W[CF * CF + idx];
    }
    int f = t & 63;
    int g = t >> 6;           // 0..3, each group handles 4 rows
    float a1f = __ldg(&a[f]);
    float a2f = __ldg(&a[CF + f]);
    __syncthreads();

    int rowBase = blockIdx.x * 64;
    for (int it = 0; it < 4; it++) {
        int r0 = rowBase + it * 16;
        // load 16 rows of x (1024 floats = 256 float4)
        ((float4*)xs)[t] = ((const float4*)(x + (size_t)r0 * CF))[t];
        __syncthreads();

        float acc0[4] = {0.f, 0.f, 0.f, 0.f};
        float acc1[4] = {0.f, 0.f, 0.f, 0.f};
        #pragma unroll 4
        for (int c = 0; c < CF; c++) {
            float w0 = W0s[c * CF + f];
            float w1 = W1s[c * CF + f];
            #pragma unroll
            for (int rr = 0; rr < 4; rr++) {
                float xv = xs[(g * 4 + rr) * CF + c];
                acc0[rr] = fmaf(xv, w0, acc0[rr]);
                acc1[rr] = fmaf(xv, w1, acc1[rr]);
            }
        }

        int lane = t & 31;
        int half = (t >> 5) & 1;
        #pragma unroll
        for (int rr = 0; rr < 4; rr++) {
            int row = r0 + g * 4 + rr;
            float h1v = acc1[rr];
            float h0v = acc0[rr];
            g_h1[(size_t)row * CF + f] = h1v;
            g_diff[(size_t)row * CF + f] = h0v - h1v;
            float hs = h0v + h1v;
            float p1 = hs * a1f;
            float p2 = hs * a2f;
            #pragma unroll
            for (int o = 16; o; o >>= 1) {
                p1 += __shfl_xor_sync(0xffffffffu, p1, o);
                p2 += __shfl_xor_sync(0xffffffffu, p2, o);
            }
            if (lane == 0) {
                redbuf[g * 4 + rr][half][0] = p1;
                redbuf[g * 4 + rr][half][1] = p2;
            }
        }
        __syncthreads();
        if (t < 16) {
            int row = r0 + t;
            g_s1[row] = redbuf[t][0][0] + redbuf[t][1][0];
            g_s2[row] = redbuf[t][0][1] + redbuf[t][1][1];
        }
        __syncthreads();
    }
}

// ---------------------------------------------------------------------------
// Kernel 2: masked softmax attention + aggregation. 1 CTA per batch.
// smem: h1 tile [512][16]f4, wt transposed [512][33], s1/s2, sums, diag, bias
// 16 phases of 32 i's; phase A = warp-local softmax; phase B = 4i x 4f x jq tile
// ---------------------------------------------------------------------------
#define SMEM_FLOATS (32768 + NN * WTS_STRIDE + NN + NN + 32 + 32 + 64)
#define SMEM_BYTES (SMEM_FLOATS * 4)

__global__ __launch_bounds__(512) void gat_attn_kernel(
    const int* __restrict__ adj, const float* __restrict__ bias,
    float* __restrict__ out)
{
    extern __shared__ float sm[];
    float4* h1s4 = (float4*)sm;                  // 512*16 float4 (32768 floats)
    float*  wts  = sm + 32768;                    // 512*33
    float*  s2s  = wts + NN * WTS_STRIDE;         // 512
    float*  s1s  = s2s + NN;                      // 512
    float*  sums = s1s + NN;                      // 32
    float*  diagw = sums + 32;                    // 32
    float*  biass = diagw + 32;                   // 64

    int b = blockIdx.x;
    int t = threadIdx.x;

    // load h1 tile for this batch (32768 floats = 8192 float4)
    {
        const float4* src = (const float4*)(g_h1 + (size_t)b * NN * CF);
        #pragma unroll
        for (int k = 0; k < 16; k++) h1s4[t + k * 512] = src[t + k * 512];
    }
    s2s[t] = g_s2[b * NN + t];
    s1s[t] = g_s1[b * NN + t];
    if (t < 64) biass[t] = bias[t];
    __syncthreads();

    int warpId = t >> 5, lane = t & 31;
    int jq = t >> 7;                // 0..3 j-quarter
    int slot = t & 127;
    int fi = slot & 15;             // float4 feature index 0..15
    int i0 = (slot >> 4) << 2;      // local i base (0,4,...,28)

    for (int ph = 0; ph < 16; ph++) {
        int iBase = ph * 32;

        // ---- Phase A: each warp computes softmax weights for 2 i's ----
        #pragma unroll
        for (int r = 0; r < 2; r++) {
            int il = (warpId << 1) | r;
            int i = iBase + il;
            float s1i = s1s[i];
            const int* arow = adj + (size_t)i * NN;
            float v[16];
            float m = -1e30f;
            #pragma unroll
            for (int k = 0; k < 16; k++) {
                int j = lane + (k << 5);
                float tv = s1i + s2s[j];
                tv = tv > 0.f ? tv : ALPHA_ * tv;
                v[k] = (__ldg(arow + j) > 0) ? tv : -1e30f;
                m = fmaxf(m, v[k]);
            }
            #pragma unroll
            for (int o = 16; o; o >>= 1)
                m = fmaxf(m, __shfl_xor_sync(0xffffffffu, m, o));
            float s = 0.f;
            #pragma unroll
            for (int k = 0; k < 16; k++) {
                float w = __expf(v[k] - m);
                s += w;
                wts[(lane + (k << 5)) * WTS_STRIDE + il] = w;
            }
            #pragma unroll
            for (int o = 16; o; o >>= 1)
                s += __shfl_xor_sync(0xffffffffu, s, o);
            if (lane == 0) sums[il] = s;
        }
        __syncthreads();

        // ---- Phase B: acc[4i][4f] over this thread's j-quarter ----
        float4 acc[4];
        acc[0] = make_float4(0.f, 0.f, 0.f, 0.f);
        acc[1] = acc[0]; acc[2] = acc[0]; acc[3] = acc[0];
        const float4* hp = h1s4 + (jq * 128) * 16 + fi;
        const float*  wp = wts + (jq * 128) * WTS_STRIDE + i0;
        #pragma unroll 4
        for (int jj = 0; jj < 128; jj++) {
            float w0 = wp[0], w1 = wp[1], w2 = wp[2], w3 = wp[3];
            float4 h = *hp;
            acc[0].x = fmaf(w0, h.x, acc[0].x);
            acc[0].y = fmaf(w0, h.y, acc[0].y);
            acc[0].z = fmaf(w0, h.z, acc[0].z);
            acc[0].w = fmaf(w0, h.w, acc[0].w);
            acc[1].x = fmaf(w1, h.x, acc[1].x);
            acc[1].y = fmaf(w1, h.y, acc[1].y);
            acc[1].z = fmaf(w1, h.z, acc[1].z);
            acc[1].w = fmaf(w1, h.w, acc[1].w);
            acc[2].x = fmaf(w2, h.x, acc[2].x);
            acc[2].y = fmaf(w2, h.y, acc[2].y);
            acc[2].z = fmaf(w2, h.z, acc[2].z);
            acc[2].w = fmaf(w2, h.w, acc[2].w);
            acc[3].x = fmaf(w3, h.x, acc[3].x);
            acc[3].y = fmaf(w3, h.y, acc[3].y);
            acc[3].z = fmaf(w3, h.z, acc[3].z);
            acc[3].w = fmaf(w3, h.w, acc[3].w);
            hp += 16;
            wp += WTS_STRIDE;
        }
        __syncthreads();   // all reads of wts done

        // extract diagonal weights before overwriting wts
        if (t < 32) diagw[t] = wts[(iBase + t) * WTS_STRIDE + t];
        __syncthreads();

        // partial reduction buffer aliased over wts region
        float4* red4 = (float4*)wts;
        #pragma unroll
        for (int aIdx = 0; aIdx < 4; aIdx++)
            red4[(jq * 32 + i0 + aIdx) * 16 + fi] = acc[aIdx];
        __syncthreads();

        // combine + diag correction + bias, write out
        {
            int il = t >> 4;
            int fc = t & 15;
            float4 tot = red4[il * 16 + fc];
            #pragma unroll
            for (int q = 1; q < 4; q++) {
                float4 p = red4[(q * 32 + il) * 16 + fc];
                tot.x += p.x; tot.y += p.y; tot.z += p.z; tot.w += p.w;
            }
            int i = iBase + il;
            float inv = 1.0f / sums[il];
            float wii = diagw[il];
            float4 df = __ldg((const float4*)g_diff + ((size_t)b * NN + i) * 16 + fc);
            float4 bs = ((const float4*)biass)[fc];
            float4 o;
            o.x = (tot.x + wii * df.x) * inv + bs.x;
            o.y = (tot.y + wii * df.y) * inv + bs.y;
            o.z = (tot.z + wii * df.z) * inv + bs.z;
            o.w = (tot.w + wii * df.w) * inv + bs.w;
            ((float4*)out)[((size_t)b * NN + i) * 16 + fc] = o;
        }
        __syncthreads();   // red region becomes wts again next phase
    }
}

// ---------------------------------------------------------------------------
extern "C" void kernel_launch(void* const* d_in, const int* in_sizes, int n_in,
                              void* d_out, int out_size) {
    const float* x    = (const float*)d_in[0];
    const int*   adj  = (const int*)d_in[1];
    const float* W    = (const float*)d_in[2];
    const float* a    = (const float*)d_in[3];
    const float* bias = (const float*)d_in[4];
    float* out = (float*)d_out;

    cudaFuncSetAttribute(gat_attn_kernel,
                         cudaFuncAttributeMaxDynamicSharedMemorySize, SMEM_BYTES);

    gat_gemm_kernel<<<(BB * NN) / 64, 256>>>(x, W, a);
    gat_attn_kernel<<<BB, 512, SMEM_BYTES>>>(adj, bias, out);
}

// round 3
// speedup vs baseline: 1.0329x; 1.0329x over previous
#include <cuda_runtime.h>

#define BB 128
#define NN 512
#define CF 64
#define ALPHA_ 0.2f
#define WTS_STRIDE 36

// scratch (allocation-free rule: __device__ globals)
__device__ __align__(16) float g_h1[BB * NN * CF];
__device__ __align__(16) float g_diff[BB * NN * CF];
__device__ float g_s1[BB * NN];
__device__ float g_s2[BB * NN];

// ---------------------------------------------------------------------------
// Kernel 1: h0 = x@W0, h1 = x@W1 ; store h1, diff=h0-h1, s1=(h0+h1)@a1, s2=...@a2
// ---------------------------------------------------------------------------
__global__ __launch_bounds__(256) void gat_gemm_kernel(
    const float* __restrict__ x, const float* __restrict__ W,
    const float* __restrict__ a)
{
    __shared__ float W0s[CF * CF];
    __shared__ float W1s[CF * CF];
    __shared__ float xs[16 * CF];
    __shared__ float redbuf[16][2][2];

    int t = threadIdx.x;
    for (int idx = t; idx < CF * CF; idx += 256) {
        W0s[idx] = W[idx];
        W1s[idx] = W[CF * CF + idx];
    }
    int f = t & 63;
    int g = t >> 6;           // 0..3, each group handles 4 rows
    float a1f = __ldg(&a[f]);
    float a2f = __ldg(&a[CF + f]);
    __syncthreads();

    int rowBase = blockIdx.x * 64;
    for (int it = 0; it < 4; it++) {
        int r0 = rowBase + it * 16;
        ((float4*)xs)[t] = ((const float4*)(x + (size_t)r0 * CF))[t];
        __syncthreads();

        float acc0[4] = {0.f, 0.f, 0.f, 0.f};
        float acc1[4] = {0.f, 0.f, 0.f, 0.f};
        #pragma unroll 4
        for (int c = 0; c < CF; c++) {
            float w0 = W0s[c * CF + f];
            float w1 = W1s[c * CF + f];
            #pragma unroll
            for (int rr = 0; rr < 4; rr++) {
                float xv = xs[(g * 4 + rr) * CF + c];
                acc0[rr] = fmaf(xv, w0, acc0[rr]);
                acc1[rr] = fmaf(xv, w1, acc1[rr]);
            }
        }

        int lane = t & 31;
        int half = (t >> 5) & 1;
        #pragma unroll
        for (int rr = 0; rr < 4; rr++) {
            int row = r0 + g * 4 + rr;
            float h1v = acc1[rr];
            float h0v = acc0[rr];
            g_h1[(size_t)row * CF + f] = h1v;
            g_diff[(size_t)row * CF + f] = h0v - h1v;
            float hs = h0v + h1v;
            float p1 = hs * a1f;
            float p2 = hs * a2f;
            #pragma unroll
            for (int o = 16; o; o >>= 1) {
                p1 += __shfl_xor_sync(0xffffffffu, p1, o);
                p2 += __shfl_xor_sync(0xffffffffu, p2, o);
            }
            if (lane == 0) {
                redbuf[g * 4 + rr][half][0] = p1;
                redbuf[g * 4 + rr][half][1] = p2;
            }
        }
        __syncthreads();
        if (t < 16) {
            int row = r0 + t;
            g_s1[row] = redbuf[t][0][0] + redbuf[t][1][0];
            g_s2[row] = redbuf[t][0][1] + redbuf[t][1][1];
        }
        __syncthreads();
    }
}

// ---------------------------------------------------------------------------
// Kernel 2: masked softmax attention + aggregation. 1 CTA per batch.
// 16 phases of 32 i's. Phase A: warp softmax -> wts[j][il] (stride 36, f4-aligned).
// Phase B: 4i x 8f x (j/8) per thread; w = 1 LDS.128, h = 2 LDS.128 (128B apart).
// ---------------------------------------------------------------------------
#define SMEM_FLOATS (32768 + NN * WTS_STRIDE + NN + NN + 32 + 32 + 64)
#define SMEM_BYTES (SMEM_FLOATS * 4)

__global__ __launch_bounds__(512) void gat_attn_kernel(
    const int* __restrict__ adj, const float* __restrict__ bias,
    float* __restrict__ out)
{
    extern __shared__ float sm[];
    float4* h1s4 = (float4*)sm;                  // 512*16 float4 (32768 floats)
    float*  wts  = sm + 32768;                    // 512*36 (73728 B)
    float*  s2s  = wts + NN * WTS_STRIDE;         // 512
    float*  s1s  = s2s + NN;                      // 512
    float*  sums = s1s + NN;                      // 32
    float*  diagw = sums + 32;                    // 32
    float*  biass = diagw + 32;                   // 64

    int b = blockIdx.x;
    int t = threadIdx.x;

    // load h1 tile for this batch (32768 floats = 8192 float4)
    {
        const float4* src = (const float4*)(g_h1 + (size_t)b * NN * CF);
        #pragma unroll
        for (int k = 0; k < 16; k++) h1s4[t + k * 512] = src[t + k * 512];
    }
    s2s[t] = g_s2[b * NN + t];
    s1s[t] = g_s1[b * NN + t];
    if (t < 64) biass[t] = bias[t];
    __syncthreads();

    int warpId = t >> 5, lane = t & 31;
    // Phase-B mapping: 8 j-slices x (8 i-groups x 8 f-pairs)
    int jq  = t >> 6;               // 0..7  (64 j's each)
    int slot = t & 63;
    int fi2 = slot & 7;             // owns float4 chunks fi2 and fi2+8
    int i0  = (slot >> 3) << 2;     // 0,4,...,28

    for (int ph = 0; ph < 16; ph++) {
        int iBase = ph * 32;

        // ---- Phase A: each warp computes softmax weights for 2 i's ----
        #pragma unroll
        for (int r = 0; r < 2; r++) {
            int il = (warpId << 1) | r;
            int i = iBase + il;
            float s1i = s1s[i];
            const int* arow = adj + (size_t)i * NN;
            float v[16];
            float m = -1e30f;
            #pragma unroll
            for (int k = 0; k < 16; k++) {
                int j = lane + (k << 5);
                float tv = s1i + s2s[j];
                tv = tv > 0.f ? tv : ALPHA_ * tv;
                v[k] = (__ldg(arow + j) > 0) ? tv : -1e30f;
                m = fmaxf(m, v[k]);
            }
            #pragma unroll
            for (int o = 16; o; o >>= 1)
                m = fmaxf(m, __shfl_xor_sync(0xffffffffu, m, o));
            float s = 0.f;
            #pragma unroll
            for (int k = 0; k < 16; k++) {
                int j = lane + (k << 5);
                float w = __expf(v[k] - m);
                s += w;
                wts[j * WTS_STRIDE + il] = w;
                if (j == i) diagw[il] = w;   // capture diagonal inline
            }
            #pragma unroll
            for (int o = 16; o; o >>= 1)
                s += __shfl_xor_sync(0xffffffffu, s, o);
            if (lane == 0) sums[il] = s;
        }
        __syncthreads();

        // ---- Phase B: acc[4i][2xfloat4] over this thread's 64-j slice ----
        float4 accA[4], accB[4];
        accA[0] = make_float4(0.f, 0.f, 0.f, 0.f);
        accA[1] = accA[0]; accA[2] = accA[0]; accA[3] = accA[0];
        accB[0] = accA[0]; accB[1] = accA[0]; accB[2] = accA[0]; accB[3] = accA[0];

        const float4* hp = h1s4 + (jq * 64) * 16 + fi2;
        const float*  wp = wts + (jq * 64) * WTS_STRIDE + i0;
        #pragma unroll 2
        for (int jj = 0; jj < 64; jj++) {
            float4 wv = *(const float4*)wp;     // w[i0..i0+3], 16B aligned
            float4 ha = hp[0];                  // features [fi2*4 .. )
            float4 hb = hp[8];                  // features [(fi2+8)*4 .. )
            accA[0].x = fmaf(wv.x, ha.x, accA[0].x);
            accA[0].y = fmaf(wv.x, ha.y, accA[0].y);
            accA[0].z = fmaf(wv.x, ha.z, accA[0].z);
            accA[0].w = fmaf(wv.x, ha.w, accA[0].w);
            accB[0].x = fmaf(wv.x, hb.x, accB[0].x);
            accB[0].y = fmaf(wv.x, hb.y, accB[0].y);
            accB[0].z = fmaf(wv.x, hb.z, accB[0].z);
            accB[0].w = fmaf(wv.x, hb.w, accB[0].w);
            accA[1].x = fmaf(wv.y, ha.x, accA[1].x);
            accA[1].y = fmaf(wv.y, ha.y, accA[1].y);
            accA[1].z = fmaf(wv.y, ha.z, accA[1].z);
            accA[1].w = fmaf(wv.y, ha.w, accA[1].w);
            accB[1].x = fmaf(wv.y, hb.x, accB[1].x);
            accB[1].y = fmaf(wv.y, hb.y, accB[1].y);
            accB[1].z = fmaf(wv.y, hb.z, accB[1].z);
            accB[1].w = fmaf(wv.y, hb.w, accB[1].w);
            accA[2].x = fmaf(wv.z, ha.x, accA[2].x);
            accA[2].y = fmaf(wv.z, ha.y, accA[2].y);
            accA[2].z = fmaf(wv.z, ha.z, accA[2].z);
            accA[2].w = fmaf(wv.z, ha.w, accA[2].w);
            accB[2].x = fmaf(wv.z, hb.x, accB[2].x);
            accB[2].y = fmaf(wv.z, hb.y, accB[2].y);
            accB[2].z = fmaf(wv.z, hb.z, accB[2].z);
            accB[2].w = fmaf(wv.z, hb.w, accB[2].w);
            accA[3].x = fmaf(wv.w, ha.x, accA[3].x);
            accA[3].y = fmaf(wv.w, ha.y, accA[3].y);
            accA[3].z = fmaf(wv.w, ha.z, accA[3].z);
            accA[3].w = fmaf(wv.w, ha.w, accA[3].w);
            accB[3].x = fmaf(wv.w, hb.x, accB[3].x);
            accB[3].y = fmaf(wv.w, hb.y, accB[3].y);
            accB[3].z = fmaf(wv.w, hb.z, accB[3].z);
            accB[3].w = fmaf(wv.w, hb.w, accB[3].w);
            hp += 16;
            wp += WTS_STRIDE;
        }
        __syncthreads();   // all reads of wts done

        // partial reduction buffer aliased over wts region (8*32*16 f4 = 64KB)
        float4* red4 = (float4*)wts;
        #pragma unroll
        for (int r = 0; r < 4; r++) {
            red4[(jq * 32 + i0 + r) * 16 + fi2]     = accA[r];
            red4[(jq * 32 + i0 + r) * 16 + fi2 + 8] = accB[r];
        }
        __syncthreads();

        // combine 8 partials + diag correction + bias, write out
        {
            int il = t >> 4;
            int fc = t & 15;
            float4 tot = red4[il * 16 + fc];
            #pragma unroll
            for (int q = 1; q < 8; q++) {
                float4 p = red4[(q * 32 + il) * 16 + fc];
                tot.x += p.x; tot.y += p.y; tot.z += p.z; tot.w += p.w;
            }
            int i = iBase + il;
            float inv = 1.0f / sums[il];
            float wii = diagw[il];
            float4 df = __ldg((const float4*)g_diff + ((size_t)b * NN + i) * 16 + fc);
            float4 bs = ((const float4*)biass)[fc];
            float4 o;
            o.x = (tot.x + wii * df.x) * inv + bs.x;
            o.y = (tot.y + wii * df.y) * inv + bs.y;
            o.z = (tot.z + wii * df.z) * inv + bs.z;
            o.w = (tot.w + wii * df.w) * inv + bs.w;
            ((float4*)out)[((size_t)b * NN + i) * 16 + fc] = o;
        }
        __syncthreads();   // red region becomes wts again next phase
    }
}

// ---------------------------------------------------------------------------
extern "C" void kernel_launch(void* const* d_in, const int* in_sizes, int n_in,
                              void* d_out, int out_size) {
    const float* x    = (const float*)d_in[0];
    const int*   adj  = (const int*)d_in[1];
    const float* W    = (const float*)d_in[2];
    const float* a    = (const float*)d_in[3];
    const float* bias = (const float*)d_in[4];
    float* out = (float*)d_out;

    cudaFuncSetAttribute(gat_attn_kernel,
                         cudaFuncAttributeMaxDynamicSharedMemorySize, SMEM_BYTES);

    gat_gemm_kernel<<<(BB * NN) / 64, 256>>>(x, W, a);
    gat_attn_kernel<<<BB, 512, SMEM_BYTES>>>(adj, bias, out);
}

// round 4
// speedup vs baseline: 1.1168x; 1.0812x over previous
#include <cuda_runtime.h>

#define BB 128
#define NN 512
#define CF 64
#define ALPHA_ 0.2f
#define WTS_STRIDE 36

typedef unsigned long long u64;

// packed f32x2 helpers (sm_100+; ptxas never emits FFMA2 from C++)
__device__ __forceinline__ void ffma2(u64 &d, u64 a, u64 b) {
    asm("fma.rn.f32x2 %0, %1, %2, %0;" : "+l"(d) : "l"(a), "l"(b));
}
__device__ __forceinline__ u64 bcast2(float w) {
    u64 r; unsigned int u = __float_as_uint(w);
    asm("mov.b64 %0, {%1, %1};" : "=l"(r) : "r"(u));
    return r;
}
__device__ __forceinline__ u64 pack2(float a, float b) {
    u64 r; asm("mov.b64 %0, {%1, %2};" : "=l"(r) : "f"(a), "f"(b));
    return r;
}
__device__ __forceinline__ float2 unpack2(u64 v) {
    float2 r; asm("mov.b64 {%0, %1}, %2;" : "=f"(r.x), "=f"(r.y) : "l"(v));
    return r;
}

// scratch (allocation-free rule: __device__ globals)
__device__ __align__(16) float g_h1[BB * NN * CF];
__device__ __align__(16) float g_diff[BB * NN * CF];
__device__ float g_s1[BB * NN];
__device__ float g_s2[BB * NN];

// ---------------------------------------------------------------------------
// Kernel 1: h0 = x@W0, h1 = x@W1 ; store h1, diff=h0-h1, s1=(h0+h1)@a1, s2=...@a2
// f32x2: pack row pairs, broadcast W. 4 FFMA2 per c per thread.
// ---------------------------------------------------------------------------
__global__ __launch_bounds__(256) void gat_gemm_kernel(
    const float* __restrict__ x, const float* __restrict__ W,
    const float* __restrict__ a)
{
    __shared__ float W0s[CF * CF];
    __shared__ float W1s[CF * CF];
    __shared__ float xs[16 * CF];
    __shared__ float redbuf[16][2][2];

    int t = threadIdx.x;
    for (int idx = t; idx < CF * CF; idx += 256) {
        W0s[idx] = W[idx];
        W1s[idx] = W[CF * CF + idx];
    }
    int f = t & 63;
    int g = t >> 6;           // 0..3, each group handles 4 rows
    float a1f = __ldg(&a[f]);
    float a2f = __ldg(&a[CF + f]);
    __syncthreads();

    int rowBase = blockIdx.x * 64;
    for (int it = 0; it < 4; it++) {
        int r0 = rowBase + it * 16;
        ((float4*)xs)[t] = ((const float4*)(x + (size_t)r0 * CF))[t];
        __syncthreads();

        u64 a0_01 = 0ULL, a0_23 = 0ULL, a1_01 = 0ULL, a1_23 = 0ULL;
        #pragma unroll 4
        for (int c = 0; c < CF; c++) {
            u64 w0p = bcast2(W0s[c * CF + f]);
            u64 w1p = bcast2(W1s[c * CF + f]);
            float x0 = xs[(g * 4 + 0) * CF + c];
            float x1 = xs[(g * 4 + 1) * CF + c];
            float x2 = xs[(g * 4 + 2) * CF + c];
            float x3 = xs[(g * 4 + 3) * CF + c];
            u64 x01 = pack2(x0, x1);
            u64 x23 = pack2(x2, x3);
            ffma2(a0_01, x01, w0p);
            ffma2(a0_23, x23, w0p);
            ffma2(a1_01, x01, w1p);
            ffma2(a1_23, x23, w1p);
        }

        float2 h0a = unpack2(a0_01), h0b = unpack2(a0_23);
        float2 h1a = unpack2(a1_01), h1b = unpack2(a1_23);
        float h0v[4] = {h0a.x, h0a.y, h0b.x, h0b.y};
        float h1v[4] = {h1a.x, h1a.y, h1b.x, h1b.y};

        int lane = t & 31;
        int half = (t >> 5) & 1;
        #pragma unroll
        for (int rr = 0; rr < 4; rr++) {
            int row = r0 + g * 4 + rr;
            g_h1[(size_t)row * CF + f] = h1v[rr];
            g_diff[(size_t)row * CF + f] = h0v[rr] - h1v[rr];
            float hs = h0v[rr] + h1v[rr];
            float p1 = hs * a1f;
            float p2 = hs * a2f;
            #pragma unroll
            for (int o = 16; o; o >>= 1) {
                p1 += __shfl_xor_sync(0xffffffffu, p1, o);
                p2 += __shfl_xor_sync(0xffffffffu, p2, o);
            }
            if (lane == 0) {
                redbuf[g * 4 + rr][half][0] = p1;
                redbuf[g * 4 + rr][half][1] = p2;
            }
        }
        __syncthreads();
        if (t < 16) {
            int row = r0 + t;
            g_s1[row] = redbuf[t][0][0] + redbuf[t][1][0];
            g_s2[row] = redbuf[t][0][1] + redbuf[t][1][1];
        }
        __syncthreads();
    }
}

// ---------------------------------------------------------------------------
// Kernel 2: masked softmax attention + aggregation. 1 CTA per batch.
// 16 phases of 32 i's. Phase A: warp softmax -> wts[j][il] (stride 36).
// Phase B: 4i x 8f x (j/8) per thread, all math as packed f32x2 (16 FFMA2/iter).
// ---------------------------------------------------------------------------
#define SMEM_FLOATS (32768 + NN * WTS_STRIDE + NN + NN + 32 + 32 + 64)
#define SMEM_BYTES (SMEM_FLOATS * 4)

__global__ __launch_bounds__(512) void gat_attn_kernel(
    const int* __restrict__ adj, const float* __restrict__ bias,
    float* __restrict__ out)
{
    extern __shared__ float sm[];
    float4* h1s4 = (float4*)sm;                  // 512*16 float4 (32768 floats)
    float*  wts  = sm + 32768;                    // 512*36
    float*  s2s  = wts + NN * WTS_STRIDE;         // 512
    float*  s1s  = s2s + NN;                      // 512
    float*  sums = s1s + NN;                      // 32
    float*  diagw = sums + 32;                    // 32
    float*  biass = diagw + 32;                   // 64

    int b = blockIdx.x;
    int t = threadIdx.x;

    {
        const float4* src = (const float4*)(g_h1 + (size_t)b * NN * CF);
        #pragma unroll
        for (int k = 0; k < 16; k++) h1s4[t + k * 512] = src[t + k * 512];
    }
    s2s[t] = g_s2[b * NN + t];
    s1s[t] = g_s1[b * NN + t];
    if (t < 64) biass[t] = bias[t];
    __syncthreads();

    int warpId = t >> 5, lane = t & 31;
    int jq  = t >> 6;               // 0..7  (64 j's each)
    int slot = t & 63;
    int fi2 = slot & 7;             // owns float4 chunks fi2 and fi2+8
    int i0  = (slot >> 3) << 2;     // 0,4,...,28

    for (int ph = 0; ph < 16; ph++) {
        int iBase = ph * 32;

        // ---- Phase A: each warp computes softmax weights for 2 i's ----
        #pragma unroll
        for (int r = 0; r < 2; r++) {
            int il = (warpId << 1) | r;
            int i = iBase + il;
            float s1i = s1s[i];
            const int* arow = adj + (size_t)i * NN;
            float v[16];
            float m = -1e30f;
            #pragma unroll
            for (int k = 0; k < 16; k++) {
                int j = lane + (k << 5);
                float tv = s1i + s2s[j];
                tv = tv > 0.f ? tv : ALPHA_ * tv;
                v[k] = (__ldg(arow + j) > 0) ? tv : -1e30f;
                m = fmaxf(m, v[k]);
            }
            #pragma unroll
            for (int o = 16; o; o >>= 1)
                m = fmaxf(m, __shfl_xor_sync(0xffffffffu, m, o));
            float s = 0.f;
            #pragma unroll
            for (int k = 0; k < 16; k++) {
                int j = lane + (k << 5);
                float w = __expf(v[k] - m);
                s += w;
                wts[j * WTS_STRIDE + il] = w;
                if (j == i) diagw[il] = w;
            }
            #pragma unroll
            for (int o = 16; o; o >>= 1)
                s += __shfl_xor_sync(0xffffffffu, s, o);
            if (lane == 0) sums[il] = s;
        }
        __syncthreads();

        // ---- Phase B: acc[4i][4 pairs] over this thread's 64-j slice ----
        u64 acc[4][4];
        #pragma unroll
        for (int r = 0; r < 4; r++)
            #pragma unroll
            for (int p = 0; p < 4; p++) acc[r][p] = 0ULL;

        const float4* hp = h1s4 + (jq * 64) * 16 + fi2;
        const float*  wp = wts + (jq * 64) * WTS_STRIDE + i0;
        #pragma unroll 4
        for (int jj = 0; jj < 64; jj++) {
            float4 wv = *(const float4*)wp;              // w[i0..i0+3]
            ulonglong2 ha = *(const ulonglong2*)(hp);    // feat pairs of chunk fi2
            ulonglong2 hb = *(const ulonglong2*)(hp + 8);// feat pairs of chunk fi2+8
            u64 w0 = bcast2(wv.x);
            u64 w1 = bcast2(wv.y);
            u64 w2 = bcast2(wv.z);
            u64 w3 = bcast2(wv.w);
            ffma2(acc[0][0], w0, ha.x); ffma2(acc[0][1], w0, ha.y);
            ffma2(acc[0][2], w0, hb.x); ffma2(acc[0][3], w0, hb.y);
            ffma2(acc[1][0], w1, ha.x); ffma2(acc[1][1], w1, ha.y);
            ffma2(acc[1][2], w1, hb.x); ffma2(acc[1][3], w1, hb.y);
            ffma2(acc[2][0], w2, ha.x); ffma2(acc[2][1], w2, ha.y);
            ffma2(acc[2][2], w2, hb.x); ffma2(acc[2][3], w2, hb.y);
            ffma2(acc[3][0], w3, ha.x); ffma2(acc[3][1], w3, ha.y);
            ffma2(acc[3][2], w3, hb.x); ffma2(acc[3][3], w3, hb.y);
            hp += 16;
            wp += WTS_STRIDE;
        }
        __syncthreads();   // all reads of wts done

        // partial reduction buffer aliased over wts region (8*32*16 f4 = 64KB)
        ulonglong2* red2 = (ulonglong2*)wts;
        #pragma unroll
        for (int r = 0; r < 4; r++) {
            ulonglong2 va; va.x = acc[r][0]; va.y = acc[r][1];
            ulonglong2 vb; vb.x = acc[r][2]; vb.y = acc[r][3];
            red2[(jq * 32 + i0 + r) * 16 + fi2]     = va;
            red2[(jq * 32 + i0 + r) * 16 + fi2 + 8] = vb;
        }
        __syncthreads();

        // combine 8 partials + diag correction + bias, write out
        {
            float4* red4 = (float4*)wts;
            int il = t >> 4;
            int fc = t & 15;
            float4 tot = red4[il * 16 + fc];
            #pragma unroll
            for (int q = 1; q < 8; q++) {
                float4 p = red4[(q * 32 + il) * 16 + fc];
                tot.x += p.x; tot.y += p.y; tot.z += p.z; tot.w += p.w;
            }
            int i = iBase + il;
            float inv = 1.0f / sums[il];
            float wii = diagw[il];
            float4 df = __ldg((const float4*)g_diff + ((size_t)b * NN + i) * 16 + fc);
            float4 bs = ((const float4*)biass)[fc];
            float4 o;
            o.x = (tot.x + wii * df.x) * inv + bs.x;
            o.y = (tot.y + wii * df.y) * inv + bs.y;
            o.z = (tot.z + wii * df.z) * inv + bs.z;
            o.w = (tot.w + wii * df.w) * inv + bs.w;
            ((float4*)out)[((size_t)b * NN + i) * 16 + fc] = o;
        }
        __syncthreads();   // red region becomes wts again next phase
    }
}

// ---------------------------------------------------------------------------
extern "C" void kernel_launch(void* const* d_in, const int* in_sizes, int n_in,
                              void* d_out, int out_size) {
    const float* x    = (const float*)d_in[0];
    const int*   adj  = (const int*)d_in[1];
    const float* W    = (const float*)d_in[2];
    const float* a    = (const float*)d_in[3];
    const float* bias = (const float*)d_in[4];
    float* out = (float*)d_out;

    cudaFuncSetAttribute(gat_attn_kernel,
                         cudaFuncAttributeMaxDynamicSharedMemorySize, SMEM_BYTES);

    gat_gemm_kernel<<<(BB * NN) / 64, 256>>>(x, W, a);
    gat_attn_kernel<<<BB, 512, SMEM_BYTES>>>(adj, bias, out);
}